// round 15
// baseline (speedup 1.0000x reference)
#include <cuda_runtime.h>
#include <cuda_fp16.h>
#include <math.h>

#define MAXN 100096
#define MAXE 1600512
#define EPS 1e-5f

// ---------------- static scratch ----------------
__device__ int    g_indeg[MAXN];
__device__ int    g_start[MAXN];
__device__ int    g_ctr;
__device__ float  g_dinv[MAXN];
__device__ int    g_rank[MAXE];
__device__ int    g_csrc[MAXE];
__device__ __half g_hA[MAXN * 64];
__device__ __half g_hB[MAXN * 64];
__device__ float  g_scal[MAXN];
__device__ float  g_bnS1[32],  g_bnT1[32];
__device__ float  g_bnS2[64],  g_bnT2[64];
__device__ float  g_bnS3[128], g_bnT3[128];
__device__ uint2  g_w1f[4 * 4 * 32];    // NT=4,  KC=4
__device__ uint2  g_w2f[8 * 2 * 32];    // NT=8,  KC=2
__device__ uint2  g_w3f[16 * 4 * 32];   // NT=16, KC=4

// ---------------- half helpers ----------------
__device__ __forceinline__ __half2 u2h(unsigned u) {
    __half2 h; *reinterpret_cast<unsigned*>(&h) = u; return h;
}
__device__ __forceinline__ unsigned h2u(__half2 h) {
    return *reinterpret_cast<unsigned*>(&h);
}

// ---------------- setup ----------------
__device__ __forceinline__ void make_frag(const float* __restrict__ W, int DOUT, int KC,
                                          uint2* __restrict__ dst, int i) {
    int nt = i / (KC * 32);
    int rem = i % (KC * 32);
    int kc = rem / 32, lane = rem % 32;
    int col = nt * 8 + (lane >> 2);
    int kb = kc * 16 + (lane & 3) * 2;
    uint2 o;
    o.x = h2u(__floats2half2_rn(W[kb * DOUT + col],       W[(kb + 1) * DOUT + col]));
    o.y = h2u(__floats2half2_rn(W[(kb + 8) * DOUT + col], W[(kb + 9) * DOUT + col]));
    dst[i] = o;
}
__device__ __forceinline__ void make_bn(const float* b, const float* g, const float* be,
                                        const float* rm, const float* rv,
                                        float* S, float* T, int j) {
    float s = g[j] * rsqrtf(rv[j] + EPS);
    S[j] = s;
    T[j] = (b[j] - rm[j]) * s + be[j];
}
// frags + BN tables ONLY — no shared mutable state with the main-stream edge chain
__global__ void prep_k(const float* W1, const float* W2, const float* W3,
                       const float* b1, const float* g1, const float* be1, const float* rm1, const float* rv1,
                       const float* b2, const float* g2, const float* be2, const float* rm2, const float* rv2,
                       const float* b3, const float* g3, const float* be3, const float* rm3, const float* rv3) {
    int i = blockIdx.x * blockDim.x + threadIdx.x;
    if (i < 512)        make_frag(W1, 32,  4, g_w1f, i);
    else if (i < 1024)  make_frag(W2, 64,  2, g_w2f, i - 512);
    else if (i < 3072)  make_frag(W3, 128, 4, g_w3f, i - 1024);
    else if (i < 3104)  make_bn(b1, g1, be1, rm1, rv1, g_bnS1, g_bnT1, i - 3072);
    else if (i < 3168)  make_bn(b2, g2, be2, rm2, rv2, g_bnS2, g_bnT2, i - 3104);
    else if (i < 3296)  make_bn(b3, g3, be3, rm3, rv3, g_bnS3, g_bnT3, i - 3168);
}

// hist + per-edge rank (atomicAdd return = slot within dst segment)
__global__ void hist_k(const int* __restrict__ ei, int e) {
    int i = blockIdx.x * blockDim.x + threadIdx.x;
    const int4* d4 = (const int4*)(ei + e);
    int q = e >> 2;
    if (i < q) {
        int4 d = d4[i];
        int4 r;
        r.x = atomicAdd(&g_indeg[d.x], 1);
        r.y = atomicAdd(&g_indeg[d.y], 1);
        r.z = atomicAdd(&g_indeg[d.z], 1);
        r.w = atomicAdd(&g_indeg[d.w], 1);
        ((int4*)g_rank)[i] = r;
    }
    int rr = q * 4 + i;
    if (i < (e & 3) && rr < e)
        g_rank[rr] = atomicAdd(&g_indeg[ei[e + rr]], 1);
}

__global__ void assign_k(int n) {
    int i = blockIdx.x * blockDim.x + threadIdx.x;
    int lane = threadIdx.x & 31;
    int deg = (i < n) ? g_indeg[i] : 0;
    if (i < n) g_dinv[i] = rsqrtf((float)(deg + 1));
    int run = deg;
#pragma unroll
    for (int off = 1; off < 32; off <<= 1) {
        int t = __shfl_up_sync(0xffffffffu, run, off);
        if (lane >= off) run += t;
    }
    int total = __shfl_sync(0xffffffffu, run, 31);
    int base = 0;
    if (lane == 31) base = atomicAdd(&g_ctr, total);
    base = __shfl_sync(0xffffffffu, base, 31);
    if (i < n) g_start[i] = base + run - deg;
}

// atomic-free scatter using precomputed ranks
__global__ void scatter_k(const int* __restrict__ ei, int e) {
    int i = blockIdx.x * blockDim.x + threadIdx.x;
    const int4* s4 = (const int4*)ei;
    const int4* d4 = (const int4*)(ei + e);
    const int4* r4 = (const int4*)g_rank;
    int q = e >> 2;
    if (i < q) {
        int4 s = s4[i], d = d4[i], r = r4[i];
        g_csrc[g_start[d.x] + r.x] = s.x;
        g_csrc[g_start[d.y] + r.y] = s.y;
        g_csrc[g_start[d.z] + r.z] = s.z;
        g_csrc[g_start[d.w] + r.w] = s.w;
    }
    int rr = q * 4 + i;
    if (i < (e & 3) && rr < e) {
        g_csrc[g_start[ei[e + rr]] + g_rank[rr]] = ei[rr];
    }
}

// ---------------- shared gather core: v[8] = dinv[node]*(self + sum neighbors) ----------------
template <int TPN>
__device__ __forceinline__ void gather_row(const uint4* __restrict__ in4, int node, int f,
                                           int lane, float* v) {
    constexpr int NB16 = 16 / TPN;
    int segbase = lane & ~(TPN - 1);
    unsigned mask = ((1u << TPN) - 1u) << segbase;
    float di = g_dinv[node];
    float se[8], ac[8];
    {
        uint4 sv = in4[(size_t)node * TPN + f];
        float2 p;
        p = __half22float2(u2h(sv.x)); se[0] = p.x; se[1] = p.y;
        p = __half22float2(u2h(sv.y)); se[2] = p.x; se[3] = p.y;
        p = __half22float2(u2h(sv.z)); se[4] = p.x; se[5] = p.y;
        p = __half22float2(u2h(sv.w)); se[6] = p.x; se[7] = p.y;
    }
#pragma unroll
    for (int j = 0; j < 8; j++) ac[j] = 0.f;
    int e0 = g_start[node], e1 = e0 + g_indeg[node];
    int e = e0;
    // batch-16: prefetch all 16 indices, gather in two halves of 8
    for (; e + 16 <= e1; e += 16) {
        int sl[NB16];
#pragma unroll
        for (int j = 0; j < NB16; j++) sl[j] = __ldg(&g_csrc[e + j * TPN + f]);
#pragma unroll
        for (int half = 0; half < 2; half++) {
            uint4 r[8];
#pragma unroll
            for (int k = 0; k < 8; k++) {
                int kk = half * 8 + k;
                int sk = __shfl_sync(mask, sl[kk / TPN], segbase + (kk % TPN), 32);
                r[k] = in4[(size_t)sk * TPN + f];
            }
#pragma unroll
            for (int k = 0; k < 8; k += 2) {
                __half2 p0 = __hadd2(u2h(r[k].x), u2h(r[k + 1].x));
                __half2 p1 = __hadd2(u2h(r[k].y), u2h(r[k + 1].y));
                __half2 p2 = __hadd2(u2h(r[k].z), u2h(r[k + 1].z));
                __half2 p3 = __hadd2(u2h(r[k].w), u2h(r[k + 1].w));
                float2 f0 = __half22float2(p0);
                float2 f1 = __half22float2(p1);
                float2 f2 = __half22float2(p2);
                float2 f3 = __half22float2(p3);
                ac[0] = fmaf(f0.x, 2.0f, ac[0]); ac[1] = fmaf(f0.y, 2.0f, ac[1]);
                ac[2] = fmaf(f1.x, 2.0f, ac[2]); ac[3] = fmaf(f1.y, 2.0f, ac[3]);
                ac[4] = fmaf(f2.x, 2.0f, ac[4]); ac[5] = fmaf(f2.y, 2.0f, ac[5]);
                ac[6] = fmaf(f3.x, 2.0f, ac[6]); ac[7] = fmaf(f3.y, 2.0f, ac[7]);
            }
        }
    }
    // batch-8 tier
    if (e + 8 <= e1) {
        constexpr int NB8 = 8 / TPN;
        int sl[NB8];
#pragma unroll
        for (int j = 0; j < NB8; j++) sl[j] = __ldg(&g_csrc[e + j * TPN + f]);
        uint4 r[8];
#pragma unroll
        for (int k = 0; k < 8; k++) {
            int sk = __shfl_sync(mask, sl[k / TPN], segbase + (k % TPN), 32);
            r[k] = in4[(size_t)sk * TPN + f];
        }
#pragma unroll
        for (int k = 0; k < 8; k += 2) {
            __half2 p0 = __hadd2(u2h(r[k].x), u2h(r[k + 1].x));
            __half2 p1 = __hadd2(u2h(r[k].y), u2h(r[k + 1].y));
            __half2 p2 = __hadd2(u2h(r[k].z), u2h(r[k + 1].z));
            __half2 p3 = __hadd2(u2h(r[k].w), u2h(r[k + 1].w));
            float2 f0 = __half22float2(p0);
            float2 f1 = __half22float2(p1);
            float2 f2 = __half22float2(p2);
            float2 f3 = __half22float2(p3);
            ac[0] = fmaf(f0.x, 2.0f, ac[0]); ac[1] = fmaf(f0.y, 2.0f, ac[1]);
            ac[2] = fmaf(f1.x, 2.0f, ac[2]); ac[3] = fmaf(f1.y, 2.0f, ac[3]);
            ac[4] = fmaf(f2.x, 2.0f, ac[4]); ac[5] = fmaf(f2.y, 2.0f, ac[5]);
            ac[6] = fmaf(f3.x, 2.0f, ac[6]); ac[7] = fmaf(f3.y, 2.0f, ac[7]);
        }
        e += 8;
    }
    // batch-4 tier
    if (e + 4 <= e1) {
        int s0 = __ldg(&g_csrc[e]),     s1 = __ldg(&g_csrc[e + 1]);
        int s2 = __ldg(&g_csrc[e + 2]), s3 = __ldg(&g_csrc[e + 3]);
        uint4 r0 = in4[(size_t)s0 * TPN + f];
        uint4 r1 = in4[(size_t)s1 * TPN + f];
        uint4 r2 = in4[(size_t)s2 * TPN + f];
        uint4 r3 = in4[(size_t)s3 * TPN + f];
        __half2 p0 = __hadd2(u2h(r0.x), u2h(r1.x));
        __half2 p1 = __hadd2(u2h(r0.y), u2h(r1.y));
        __half2 p2 = __hadd2(u2h(r0.z), u2h(r1.z));
        __half2 p3 = __hadd2(u2h(r0.w), u2h(r1.w));
        __half2 q0 = __hadd2(u2h(r2.x), u2h(r3.x));
        __half2 q1 = __hadd2(u2h(r2.y), u2h(r3.y));
        __half2 q2 = __hadd2(u2h(r2.z), u2h(r3.z));
        __half2 q3 = __hadd2(u2h(r2.w), u2h(r3.w));
        float2 fa, fb;
        fa = __half22float2(p0); fb = __half22float2(q0);
        ac[0] = fmaf(fa.x + fb.x, 2.0f, ac[0]); ac[1] = fmaf(fa.y + fb.y, 2.0f, ac[1]);
        fa = __half22float2(p1); fb = __half22float2(q1);
        ac[2] = fmaf(fa.x + fb.x, 2.0f, ac[2]); ac[3] = fmaf(fa.y + fb.y, 2.0f, ac[3]);
        fa = __half22float2(p2); fb = __half22float2(q2);
        ac[4] = fmaf(fa.x + fb.x, 2.0f, ac[4]); ac[5] = fmaf(fa.y + fb.y, 2.0f, ac[5]);
        fa = __half22float2(p3); fb = __half22float2(q3);
        ac[6] = fmaf(fa.x + fb.x, 2.0f, ac[6]); ac[7] = fmaf(fa.y + fb.y, 2.0f, ac[7]);
        e += 4;
    }
    for (; e < e1; e++) {
        int s = __ldg(&g_csrc[e]);
        uint4 r = in4[(size_t)s * TPN + f];
        float2 p;
        p = __half22float2(u2h(r.x)); se[0] += p.x; se[1] += p.y;
        p = __half22float2(u2h(r.y)); se[2] += p.x; se[3] += p.y;
        p = __half22float2(u2h(r.z)); se[4] += p.x; se[5] += p.y;
        p = __half22float2(u2h(r.w)); se[6] += p.x; se[7] += p.y;
    }
#pragma unroll
    for (int j = 0; j < 8; j++) v[j] = fmaf(ac[j], 0.5f, se[j]) * di;
}

// ---------------- layer-1 agg: gather + BN/ELU + *dinv -> half ----------------
__global__ void agg1_k(const __half* __restrict__ in_, __half* __restrict__ out_, int n) {
    const uint4* in4 = (const uint4*)in_;
    uint4* out4 = (uint4*)out_;
    int tid = blockIdx.x * blockDim.x + threadIdx.x;
    int node = tid / 4, f = tid % 4;
    if (node >= n) return;
    int lane = threadIdx.x & 31;
    float v[8];
    gather_row<4>(in4, node, f, lane, v);
    float di = g_dinv[node];
    float4 sA = ((const float4*)g_bnS1)[f * 2];
    float4 sB = ((const float4*)g_bnS1)[f * 2 + 1];
    float4 tA = ((const float4*)g_bnT1)[f * 2];
    float4 tB = ((const float4*)g_bnT1)[f * 2 + 1];
    float s[8] = {sA.x, sA.y, sA.z, sA.w, sB.x, sB.y, sB.z, sB.w};
    float t[8] = {tA.x, tA.y, tA.z, tA.w, tB.x, tB.y, tB.z, tB.w};
#pragma unroll
    for (int j = 0; j < 8; j++) {
        float u = v[j] * s[j] + t[j];
        u = (u > 0.f) ? u : expm1f(u);
        v[j] = u * di;
    }
    uint4 o;
    o.x = h2u(__floats2half2_rn(v[0], v[1]));
    o.y = h2u(__floats2half2_rn(v[2], v[3]));
    o.z = h2u(__floats2half2_rn(v[4], v[5]));
    o.w = h2u(__floats2half2_rn(v[6], v[7]));
    out4[(size_t)node * 4 + f] = o;
}

// ---------------- fused agg + tensor-core GEMM (layers 2, 3+4) ----------------
template <int DIN, int DOUT, int EPI>
__global__ void agg_gemm_k(const __half* __restrict__ in_, const uint2* __restrict__ wfrag,
                           const float* __restrict__ bnS, const float* __restrict__ bnT,
                           const float* __restrict__ W4, void* __restrict__ out_, int n) {
    constexpr int KC = DIN / 16;
    constexpr int NT = DOUT / 8;
    constexpr int STR = DIN + 4;
    constexpr int TPN = DIN / 8;
    constexpr int NPN = 256 / TPN;
    constexpr int NPASS = 128 / NPN;
    __shared__ __half As[128 * STR];
    __shared__ uint2  Bs[NT * KC * 32];
    int tid = threadIdx.x, wid = tid >> 5, lane = tid & 31;
    int rowbase = blockIdx.x * 128;
    for (int i = tid; i < NT * KC * 32; i += 256) Bs[i] = wfrag[i];

    const uint4* in4 = (const uint4*)in_;
    int f = tid % TPN;
#pragma unroll
    for (int pass = 0; pass < NPASS; pass++) {
        int noderow = pass * NPN + tid / TPN;
        int node = rowbase + noderow;
        float v[8];
        if (node < n) {
            gather_row<TPN>(in4, node, f, lane, v);
        } else {
#pragma unroll
            for (int j = 0; j < 8; j++) v[j] = 0.f;
        }
        __half* p = &As[noderow * STR + f * 8];
        ((uint2*)p)[0] = make_uint2(h2u(__floats2half2_rn(v[0], v[1])),
                                    h2u(__floats2half2_rn(v[2], v[3])));
        ((uint2*)p)[1] = make_uint2(h2u(__floats2half2_rn(v[4], v[5])),
                                    h2u(__floats2half2_rn(v[6], v[7])));
    }
    __syncthreads();

    int g = lane >> 2, t = lane & 3;
    int r0 = wid * 16 + g;
    unsigned a[KC][4];
#pragma unroll
    for (int kc = 0; kc < KC; kc++) {
        int kb = kc * 16 + t * 2;
        a[kc][0] = *(const unsigned*)&As[r0 * STR + kb];
        a[kc][1] = *(const unsigned*)&As[(r0 + 8) * STR + kb];
        a[kc][2] = *(const unsigned*)&As[r0 * STR + kb + 8];
        a[kc][3] = *(const unsigned*)&As[(r0 + 8) * STR + kb + 8];
    }
    int grow0 = rowbase + r0, grow1 = grow0 + 8;
    float di0 = (grow0 < n) ? g_dinv[grow0] : 0.f;
    float di1 = (grow1 < n) ? g_dinv[grow1] : 0.f;
    float accR0 = 0.f, accR1 = 0.f;
#pragma unroll
    for (int nt = 0; nt < NT; nt++) {
        float c0 = 0.f, c1 = 0.f, c2 = 0.f, c3 = 0.f;
#pragma unroll
        for (int kc = 0; kc < KC; kc++) {
            uint2 b = Bs[(nt * KC + kc) * 32 + lane];
            asm volatile(
                "mma.sync.aligned.m16n8k16.row.col.f32.f16.f16.f32 "
                "{%0,%1,%2,%3}, {%4,%5,%6,%7}, {%8,%9}, {%0,%1,%2,%3};\n"
                : "+f"(c0), "+f"(c1), "+f"(c2), "+f"(c3)
                : "r"(a[kc][0]), "r"(a[kc][1]), "r"(a[kc][2]), "r"(a[kc][3]),
                  "r"(b.x), "r"(b.y));
        }
        int col = nt * 8 + t * 2;
        float s0 = bnS[col], s1 = bnS[col + 1];
        float t0 = bnT[col], t1 = bnT[col + 1];
        c0 = c0 * s0 + t0; c1 = c1 * s1 + t1;
        c2 = c2 * s0 + t0; c3 = c3 * s1 + t1;
        c0 = (c0 > 0.f) ? c0 : expm1f(c0);
        c1 = (c1 > 0.f) ? c1 : expm1f(c1);
        c2 = (c2 > 0.f) ? c2 : expm1f(c2);
        c3 = (c3 > 0.f) ? c3 : expm1f(c3);
        if (EPI == 3) {
            float w0 = __ldg(&W4[col]), w1 = __ldg(&W4[col + 1]);
            accR0 += c0 * w0 + c1 * w1;
            accR1 += c2 * w0 + c3 * w1;
        } else {
            c0 *= di0; c1 *= di0; c2 *= di1; c3 *= di1;
            __half* out = (__half*)out_;
            if (grow0 < n)
                *(unsigned*)&out[(size_t)grow0 * DOUT + col] = h2u(__floats2half2_rn(c0, c1));
            if (grow1 < n)
                *(unsigned*)&out[(size_t)grow1 * DOUT + col] = h2u(__floats2half2_rn(c2, c3));
        }
    }
    if (EPI == 3) {
        accR0 += __shfl_xor_sync(0xffffffffu, accR0, 1);
        accR0 += __shfl_xor_sync(0xffffffffu, accR0, 2);
        accR1 += __shfl_xor_sync(0xffffffffu, accR1, 1);
        accR1 += __shfl_xor_sync(0xffffffffu, accR1, 2);
        float* scal = (float*)out_;
        if (t == 0) {
            if (grow0 < n) scal[grow0] = accR0 * di0;
            if (grow1 < n) scal[grow1] = accR1 * di1;
        }
    }
}

// ---------------- layer-1 GEMM (fp32 in, tensor core) ----------------
__global__ void gemm1_k(const float* __restrict__ in_, const uint2* __restrict__ wfrag,
                        __half* __restrict__ out, int n) {
    constexpr int DIN = 64, DOUT = 32, KC = 4, NT = 4, STR = DIN + 4;
    __shared__ __half As[128 * STR];
    __shared__ uint2  Bs[NT * KC * 32];
    int tid = threadIdx.x, wid = tid >> 5, lane = tid & 31;
    int rowbase = blockIdx.x * 128;
    for (int i = tid; i < NT * KC * 32; i += 256) Bs[i] = wfrag[i];
    constexpr int CPR = DIN / 4;
    const float4* src = (const float4*)in_;
    for (int c = tid; c < 128 * CPR; c += 256) {
        int r = c / CPR, q = c % CPR;
        float4 v = (rowbase + r < n) ? src[(size_t)(rowbase + r) * CPR + q]
                                     : make_float4(0.f, 0.f, 0.f, 0.f);
        uint2 o;
        o.x = h2u(__floats2half2_rn(v.x, v.y));
        o.y = h2u(__floats2half2_rn(v.z, v.w));
        *(uint2*)&As[r * STR + q * 4] = o;
    }
    __syncthreads();
    int g = lane >> 2, t = lane & 3;
    int r0 = wid * 16 + g;
    unsigned a[KC][4];
#pragma unroll
    for (int kc = 0; kc < KC; kc++) {
        int kb = kc * 16 + t * 2;
        a[kc][0] = *(const unsigned*)&As[r0 * STR + kb];
        a[kc][1] = *(const unsigned*)&As[(r0 + 8) * STR + kb];
        a[kc][2] = *(const unsigned*)&As[r0 * STR + kb + 8];
        a[kc][3] = *(const unsigned*)&As[(r0 + 8) * STR + kb + 8];
    }
    int grow0 = rowbase + r0, grow1 = grow0 + 8;
    float di0 = (grow0 < n) ? g_dinv[grow0] : 0.f;
    float di1 = (grow1 < n) ? g_dinv[grow1] : 0.f;
#pragma unroll
    for (int nt = 0; nt < NT; nt++) {
        float c0 = 0.f, c1 = 0.f, c2 = 0.f, c3 = 0.f;
#pragma unroll
        for (int kc = 0; kc < KC; kc++) {
            uint2 b = Bs[(nt * KC + kc) * 32 + lane];
            asm volatile(
                "mma.sync.aligned.m16n8k16.row.col.f32.f16.f16.f32 "
                "{%0,%1,%2,%3}, {%4,%5,%6,%7}, {%8,%9}, {%0,%1,%2,%3};\n"
                : "+f"(c0), "+f"(c1), "+f"(c2), "+f"(c3)
                : "r"(a[kc][0]), "r"(a[kc][1]), "r"(a[kc][2]), "r"(a[kc][3]),
                  "r"(b.x), "r"(b.y));
        }
        int col = nt * 8 + t * 2;
        c0 *= di0; c1 *= di0; c2 *= di1; c3 *= di1;
        if (grow0 < n)
            *(unsigned*)&out[(size_t)grow0 * DOUT + col] = h2u(__floats2half2_rn(c0, c1));
        if (grow1 < n)
            *(unsigned*)&out[(size_t)grow1 * DOUT + col] = h2u(__floats2half2_rn(c2, c3));
    }
}

// last layer: scalar rows, batch-8; v = di*(self+sum)+b, ELU, sigmoid
__global__ void agg_last_k(const float* __restrict__ in, const float* __restrict__ b,
                           float* __restrict__ out, int n) {
    int node = blockIdx.x * blockDim.x + threadIdx.x;
    if (node >= n) return;
    float di = g_dinv[node];
    float a0 = in[node], a1 = 0.f, a2 = 0.f, a3 = 0.f;
    float a4 = 0.f, a5 = 0.f, a6 = 0.f, a7 = 0.f;
    int e0 = g_start[node], e1 = e0 + g_indeg[node];
    int e = e0;
    for (; e + 8 <= e1; e += 8) {
        int s0 = __ldg(&g_csrc[e]),     s1 = __ldg(&g_csrc[e + 1]);
        int s2 = __ldg(&g_csrc[e + 2]), s3 = __ldg(&g_csrc[e + 3]);
        int s4 = __ldg(&g_csrc[e + 4]), s5 = __ldg(&g_csrc[e + 5]);
        int s6 = __ldg(&g_csrc[e + 6]), s7 = __ldg(&g_csrc[e + 7]);
        a0 += in[s0]; a1 += in[s1]; a2 += in[s2]; a3 += in[s3];
        a4 += in[s4]; a5 += in[s5]; a6 += in[s6]; a7 += in[s7];
    }
    if (e + 4 <= e1) {
        int s0 = __ldg(&g_csrc[e]),     s1 = __ldg(&g_csrc[e + 1]);
        int s2 = __ldg(&g_csrc[e + 2]), s3 = __ldg(&g_csrc[e + 3]);
        a4 += in[s0]; a5 += in[s1]; a6 += in[s2]; a7 += in[s3];
        e += 4;
    }
    for (; e < e1; e++) a0 += in[__ldg(&g_csrc[e])];
    float v = (((a0 + a1) + (a2 + a3)) + ((a4 + a5) + (a6 + a7))) * di + b[0];
    v = (v > 0.f) ? v : expm1f(v);
    out[node] = 1.f / (1.f + expf(-v));
}

// ---------------- launch ----------------
extern "C" void kernel_launch(void* const* d_in, const int* in_sizes, int n_in,
                              void* d_out, int out_size) {
    const float* x  = (const float*)d_in[0];
    const int*   ei = (const int*)d_in[1];
    const float* W1 = (const float*)d_in[2];  const float* b1 = (const float*)d_in[3];
    const float* W2 = (const float*)d_in[4];  const float* b2 = (const float*)d_in[5];
    const float* W3 = (const float*)d_in[6];  const float* b3 = (const float*)d_in[7];
    const float* W4 = (const float*)d_in[8];  const float* b4 = (const float*)d_in[9];
    const float* g1 = (const float*)d_in[10]; const float* be1 = (const float*)d_in[11];
    const float* rm1 = (const float*)d_in[12]; const float* rv1 = (const float*)d_in[13];
    const float* g2 = (const float*)d_in[14]; const float* be2 = (const float*)d_in[15];
    const float* rm2 = (const float*)d_in[16]; const float* rv2 = (const float*)d_in[17];
    const float* g3 = (const float*)d_in[18]; const float* be3 = (const float*)d_in[19];
    const float* rm3 = (const float*)d_in[20]; const float* rv3 = (const float*)d_in[21];

    int n = in_sizes[0] / 64;       // 100000
    int e = in_sizes[1] / 2;        // 1600000

    __half* hA; cudaGetSymbolAddress((void**)&hA, g_hA);
    __half* hB; cudaGetSymbolAddress((void**)&hB, g_hB);
    float* scal; cudaGetSymbolAddress((void**)&scal, g_scal);
    int* indegp; cudaGetSymbolAddress((void**)&indegp, g_indeg);
    int* ctrp;  cudaGetSymbolAddress((void**)&ctrp, g_ctr);
    uint2* w1f; cudaGetSymbolAddress((void**)&w1f, g_w1f);
    uint2* w2f; cudaGetSymbolAddress((void**)&w2f, g_w2f);
    uint2* w3f; cudaGetSymbolAddress((void**)&w3f, g_w3f);
    float* bnS2; cudaGetSymbolAddress((void**)&bnS2, g_bnS2);
    float* bnT2; cudaGetSymbolAddress((void**)&bnT2, g_bnT2);
    float* bnS3; cudaGetSymbolAddress((void**)&bnS3, g_bnS3);
    float* bnT3; cudaGetSymbolAddress((void**)&bnT3, g_bnT3);
    float* out = (float*)d_out;

    int nb_n  = (n + 255) / 256;
    int nb_e4 = (e / 4 + 255) / 256;
    int nb_g  = (n + 127) / 128;

    cudaStream_t s2;
    cudaStreamCreateWithFlags(&s2, cudaStreamNonBlocking);
    cudaEvent_t evA, evG;
    cudaEventCreateWithFlags(&evA, cudaEventDisableTiming);
    cudaEventCreateWithFlags(&evG, cudaEventDisableTiming);

    // main stream: zero indeg + ctr (ordered before hist/assign in-stream)
    cudaMemsetAsync(indegp, 0, MAXN * sizeof(int), 0);
    cudaMemsetAsync(ctrp, 0, sizeof(int), 0);
    // side stream: prep (frags + BN) — touches only frag/BN state
    prep_k<<<13, 256, 0, s2>>>(W1, W2, W3,
                               b1, g1, be1, rm1, rv1,
                               b2, g2, be2, rm2, rv2,
                               b3, g3, be3, rm3, rv3);

    hist_k<<<nb_e4, 256>>>(ei, e);            // indeg + per-edge rank
    assign_k<<<nb_n, 256>>>(n);               // dinv + segment starts (uses ctr, main stream)
    cudaEventRecord(evA, 0);

    // gemm1 on side stream: in-stream after prep; waits on assign (dinv)
    cudaStreamWaitEvent(s2, evA, 0);
    gemm1_k<<<nb_g, 256, 0, s2>>>(x, w1f, hA, n);
    cudaEventRecord(evG, s2);

    scatter_k<<<nb_e4, 256>>>(ei, e);         // atomic-free
    cudaStreamWaitEvent(0, evG, 0);

    // layer 1 agg (+BN/ELU, *dinv): hA -> hB (w32)
    agg1_k<<<(n * 4 + 255) / 256, 256>>>(hA, hB, n);

    // layer 2 fused agg+gemm: gather hB (w32) -> 32->64 +BN/ELU *dinv -> hA (w64)
    agg_gemm_k<32, 64, 1><<<nb_g, 256>>>(hB, w2f, bnS2, bnT2, 0, hA, n);

    // layer 3+4 fused agg+gemm: gather hA (w64) -> 64->128 +BN/ELU .W4 *dinv -> scal
    agg_gemm_k<64, 128, 3><<<nb_g, 256>>>(hA, w3f, bnS3, bnT3, W4, scal, n);

    // final agg + bias + ELU + sigmoid
    agg_last_k<<<nb_n, 256>>>(scal, b4, out, n);
}

// round 17
// speedup vs baseline: 1.0528x; 1.0528x over previous
#include <cuda_runtime.h>
#include <cuda_fp16.h>
#include <math.h>

#define MAXN 100096
#define MAXE 1600512
#define EPS 1e-5f

// ---------------- static scratch ----------------
__device__ int    g_indeg[MAXN];
__device__ int    g_start[MAXN];
__device__ int    g_ctr;
__device__ float  g_dinv[MAXN];
__device__ int    g_rank[MAXE];
__device__ int    g_csrc[MAXE];
__device__ __half g_hA[MAXN * 64];
__device__ __half g_hB[MAXN * 64];
__device__ float  g_scal[MAXN];
__device__ float  g_bnS1[32],  g_bnT1[32];
__device__ float  g_bnS2[64],  g_bnT2[64];
__device__ float  g_bnS3[128], g_bnT3[128];
__device__ uint2  g_w1f[4 * 4 * 32];    // NT=4,  KC=4
__device__ uint2  g_w2f[8 * 2 * 32];    // NT=8,  KC=2
__device__ uint2  g_w3f[16 * 4 * 32];   // NT=16, KC=4

// ---------------- half helpers ----------------
__device__ __forceinline__ __half2 u2h(unsigned u) {
    __half2 h; *reinterpret_cast<unsigned*>(&h) = u; return h;
}
__device__ __forceinline__ unsigned h2u(__half2 h) {
    return *reinterpret_cast<unsigned*>(&h);
}

// ---------------- setup ----------------
__global__ void init_k(int n) {
    int i = blockIdx.x * blockDim.x + threadIdx.x;
    if (i < MAXN) g_indeg[i] = 0;
    if (i == 0) g_ctr = 0;
}

__device__ __forceinline__ void make_frag(const float* __restrict__ W, int DOUT, int KC,
                                          uint2* __restrict__ dst, int i) {
    int nt = i / (KC * 32);
    int rem = i % (KC * 32);
    int kc = rem / 32, lane = rem % 32;
    int col = nt * 8 + (lane >> 2);
    int kb = kc * 16 + (lane & 3) * 2;
    uint2 o;
    o.x = h2u(__floats2half2_rn(W[kb * DOUT + col],       W[(kb + 1) * DOUT + col]));
    o.y = h2u(__floats2half2_rn(W[(kb + 8) * DOUT + col], W[(kb + 9) * DOUT + col]));
    dst[i] = o;
}
__device__ __forceinline__ void make_bn(const float* b, const float* g, const float* be,
                                        const float* rm, const float* rv,
                                        float* S, float* T, int j) {
    float s = g[j] * rsqrtf(rv[j] + EPS);
    S[j] = s;
    T[j] = (b[j] - rm[j]) * s + be[j];
}
// frags + BN tables ONLY — no shared mutable state with the main-stream edge chain
__global__ void prep_k(const float* W1, const float* W2, const float* W3,
                       const float* b1, const float* g1, const float* be1, const float* rm1, const float* rv1,
                       const float* b2, const float* g2, const float* be2, const float* rm2, const float* rv2,
                       const float* b3, const float* g3, const float* be3, const float* rm3, const float* rv3) {
    int i = blockIdx.x * blockDim.x + threadIdx.x;
    if (i < 512)        make_frag(W1, 32,  4, g_w1f, i);
    else if (i < 1024)  make_frag(W2, 64,  2, g_w2f, i - 512);
    else if (i < 3072)  make_frag(W3, 128, 4, g_w3f, i - 1024);
    else if (i < 3104)  make_bn(b1, g1, be1, rm1, rv1, g_bnS1, g_bnT1, i - 3072);
    else if (i < 3168)  make_bn(b2, g2, be2, rm2, rv2, g_bnS2, g_bnT2, i - 3104);
    else if (i < 3296)  make_bn(b3, g3, be3, rm3, rv3, g_bnS3, g_bnT3, i - 3168);
}

// hist + per-edge rank (atomicAdd return = slot within dst segment)
__global__ void hist_k(const int* __restrict__ ei, int e) {
    int i = blockIdx.x * blockDim.x + threadIdx.x;
    const int4* d4 = (const int4*)(ei + e);
    int q = e >> 2;
    if (i < q) {
        int4 d = d4[i];
        int4 r;
        r.x = atomicAdd(&g_indeg[d.x], 1);
        r.y = atomicAdd(&g_indeg[d.y], 1);
        r.z = atomicAdd(&g_indeg[d.z], 1);
        r.w = atomicAdd(&g_indeg[d.w], 1);
        ((int4*)g_rank)[i] = r;
    }
    int rr = q * 4 + i;
    if (i < (e & 3) && rr < e)
        g_rank[rr] = atomicAdd(&g_indeg[ei[e + rr]], 1);
}

__global__ void assign_k(int n) {
    int i = blockIdx.x * blockDim.x + threadIdx.x;
    int lane = threadIdx.x & 31;
    int deg = (i < n) ? g_indeg[i] : 0;
    if (i < n) g_dinv[i] = rsqrtf((float)(deg + 1));
    int run = deg;
#pragma unroll
    for (int off = 1; off < 32; off <<= 1) {
        int t = __shfl_up_sync(0xffffffffu, run, off);
        if (lane >= off) run += t;
    }
    int total = __shfl_sync(0xffffffffu, run, 31);
    int base = 0;
    if (lane == 31) base = atomicAdd(&g_ctr, total);
    base = __shfl_sync(0xffffffffu, base, 31);
    if (i < n) g_start[i] = base + run - deg;
}

// atomic-free scatter using precomputed ranks
__global__ void scatter_k(const int* __restrict__ ei, int e) {
    int i = blockIdx.x * blockDim.x + threadIdx.x;
    const int4* s4 = (const int4*)ei;
    const int4* d4 = (const int4*)(ei + e);
    const int4* r4 = (const int4*)g_rank;
    int q = e >> 2;
    if (i < q) {
        int4 s = s4[i], d = d4[i], r = r4[i];
        g_csrc[g_start[d.x] + r.x] = s.x;
        g_csrc[g_start[d.y] + r.y] = s.y;
        g_csrc[g_start[d.z] + r.z] = s.z;
        g_csrc[g_start[d.w] + r.w] = s.w;
    }
    int rr = q * 4 + i;
    if (i < (e & 3) && rr < e) {
        g_csrc[g_start[ei[e + rr]] + g_rank[rr]] = ei[rr];
    }
}

// ---------------- aggregation (half rows, f32 accumulators, batch-8/4) ----------------
// rows pre-scaled by dinv[src]; result = dinv[node]*(self + sum)
// EPI 0: store half. EPI 1: fused BN1, ELU, *dinv, store half.
template <int TPN, int EPI>
__global__ void agg_h_k(const __half* __restrict__ in_, __half* __restrict__ out_, int n) {
    constexpr int NB = 8 / TPN;
    const uint4* in4 = (const uint4*)in_;
    uint4* out4 = (uint4*)out_;
    int tid = blockIdx.x * blockDim.x + threadIdx.x;
    int node = tid / TPN, f = tid % TPN;
    if (node >= n) return;
    int lane = threadIdx.x & 31;
    int segbase = lane & ~(TPN - 1);
    unsigned mask = ((1u << TPN) - 1u) << segbase;
    float di = g_dinv[node];
    float se[8], ac[8];
    {
        uint4 sv = in4[(size_t)node * TPN + f];
        float2 p;
        p = __half22float2(u2h(sv.x)); se[0] = p.x; se[1] = p.y;
        p = __half22float2(u2h(sv.y)); se[2] = p.x; se[3] = p.y;
        p = __half22float2(u2h(sv.z)); se[4] = p.x; se[5] = p.y;
        p = __half22float2(u2h(sv.w)); se[6] = p.x; se[7] = p.y;
    }
#pragma unroll
    for (int j = 0; j < 8; j++) ac[j] = 0.f;
    int e0 = g_start[node], e1 = e0 + g_indeg[node];
    int e = e0;
    for (; e + 8 <= e1; e += 8) {
        int sl[NB];
#pragma unroll
        for (int j = 0; j < NB; j++) sl[j] = __ldg(&g_csrc[e + j * TPN + f]);
        uint4 r[8];
#pragma unroll
        for (int k = 0; k < 8; k++) {
            int sk = __shfl_sync(mask, sl[k / TPN], segbase + (k % TPN), 32);
            r[k] = in4[(size_t)sk * TPN + f];
        }
#pragma unroll
        for (int k = 0; k < 8; k += 2) {
            __half2 p0 = __hadd2(u2h(r[k].x), u2h(r[k + 1].x));
            __half2 p1 = __hadd2(u2h(r[k].y), u2h(r[k + 1].y));
            __half2 p2 = __hadd2(u2h(r[k].z), u2h(r[k + 1].z));
            __half2 p3 = __hadd2(u2h(r[k].w), u2h(r[k + 1].w));
            float2 f0 = __half22float2(p0);
            float2 f1 = __half22float2(p1);
            float2 f2 = __half22float2(p2);
            float2 f3 = __half22float2(p3);
            ac[0] = fmaf(f0.x, 2.0f, ac[0]); ac[1] = fmaf(f0.y, 2.0f, ac[1]);
            ac[2] = fmaf(f1.x, 2.0f, ac[2]); ac[3] = fmaf(f1.y, 2.0f, ac[3]);
            ac[4] = fmaf(f2.x, 2.0f, ac[4]); ac[5] = fmaf(f2.y, 2.0f, ac[5]);
            ac[6] = fmaf(f3.x, 2.0f, ac[6]); ac[7] = fmaf(f3.y, 2.0f, ac[7]);
        }
    }
    if (e + 4 <= e1) {
        int s0 = __ldg(&g_csrc[e]),     s1 = __ldg(&g_csrc[e + 1]);
        int s2 = __ldg(&g_csrc[e + 2]), s3 = __ldg(&g_csrc[e + 3]);
        uint4 r0 = in4[(size_t)s0 * TPN + f];
        uint4 r1 = in4[(size_t)s1 * TPN + f];
        uint4 r2 = in4[(size_t)s2 * TPN + f];
        uint4 r3 = in4[(size_t)s3 * TPN + f];
        __half2 p0 = __hadd2(u2h(r0.x), u2h(r1.x));
        __half2 p1 = __hadd2(u2h(r0.y), u2h(r1.y));
        __half2 p2 = __hadd2(u2h(r0.z), u2h(r1.z));
        __half2 p3 = __hadd2(u2h(r0.w), u2h(r1.w));
        __half2 q0 = __hadd2(u2h(r2.x), u2h(r3.x));
        __half2 q1 = __hadd2(u2h(r2.y), u2h(r3.y));
        __half2 q2 = __hadd2(u2h(r2.z), u2h(r3.z));
        __half2 q3 = __hadd2(u2h(r2.w), u2h(r3.w));
        float2 fa, fb;
        fa = __half22float2(p0); fb = __half22float2(q0);
        ac[0] = fmaf(fa.x + fb.x, 2.0f, ac[0]); ac[1] = fmaf(fa.y + fb.y, 2.0f, ac[1]);
        fa = __half22float2(p1); fb = __half22float2(q1);
        ac[2] = fmaf(fa.x + fb.x, 2.0f, ac[2]); ac[3] = fmaf(fa.y + fb.y, 2.0f, ac[3]);
        fa = __half22float2(p2); fb = __half22float2(q2);
        ac[4] = fmaf(fa.x + fb.x, 2.0f, ac[4]); ac[5] = fmaf(fa.y + fb.y, 2.0f, ac[5]);
        fa = __half22float2(p3); fb = __half22float2(q3);
        ac[6] = fmaf(fa.x + fb.x, 2.0f, ac[6]); ac[7] = fmaf(fa.y + fb.y, 2.0f, ac[7]);
        e += 4;
    }
    for (; e < e1; e++) {
        int s = __ldg(&g_csrc[e]);
        uint4 r = in4[(size_t)s * TPN + f];
        float2 p;
        p = __half22float2(u2h(r.x)); se[0] += p.x; se[1] += p.y;
        p = __half22float2(u2h(r.y)); se[2] += p.x; se[3] += p.y;
        p = __half22float2(u2h(r.z)); se[4] += p.x; se[5] += p.y;
        p = __half22float2(u2h(r.w)); se[6] += p.x; se[7] += p.y;
    }
    float v[8];
#pragma unroll
    for (int j = 0; j < 8; j++) v[j] = fmaf(ac[j], 0.5f, se[j]) * di;
    if (EPI == 1) {
        float4 sA = ((const float4*)g_bnS1)[f * 2];
        float4 sB = ((const float4*)g_bnS1)[f * 2 + 1];
        float4 tA = ((const float4*)g_bnT1)[f * 2];
        float4 tB = ((const float4*)g_bnT1)[f * 2 + 1];
        float s[8] = {sA.x, sA.y, sA.z, sA.w, sB.x, sB.y, sB.z, sB.w};
        float t[8] = {tA.x, tA.y, tA.z, tA.w, tB.x, tB.y, tB.z, tB.w};
#pragma unroll
        for (int j = 0; j < 8; j++) {
            float u = v[j] * s[j] + t[j];
            u = (u > 0.f) ? u : expm1f(u);
            v[j] = u * di;
        }
    }
    uint4 o;
    o.x = h2u(__floats2half2_rn(v[0], v[1]));
    o.y = h2u(__floats2half2_rn(v[2], v[3]));
    o.z = h2u(__floats2half2_rn(v[4], v[5]));
    o.w = h2u(__floats2half2_rn(v[6], v[7]));
    out4[(size_t)node * TPN + f] = o;
}

// ---------------- tensor-core GEMM: 128 rows/block, mma.m16n8k16 ----------------
// EPI: 0 = acc*dinv (half out)   1 = ELU(BN(acc))*dinv (half out)
//      3 = fused L3+L4: scal[row] = (ELU(BN(acc)) . W4) * dinv (float out)
template <int DIN, int DOUT, int EPI, bool IN_HALF>
__global__ void gemm_mma_k(const void* __restrict__ in_, const uint2* __restrict__ wfrag,
                           const float* __restrict__ bnS, const float* __restrict__ bnT,
                           const float* __restrict__ W4, void* __restrict__ out_, int n) {
    constexpr int KC = DIN / 16;
    constexpr int NT = DOUT / 8;
    constexpr int STR = DIN + 4;
    __shared__ __half As[128 * STR];
    __shared__ uint2  Bs[NT * KC * 32];
    int tid = threadIdx.x, wid = tid >> 5, lane = tid & 31;
    int rowbase = blockIdx.x * 128;

    for (int i = tid; i < NT * KC * 32; i += 256) Bs[i] = wfrag[i];

    if (IN_HALF) {
        constexpr int CPR = DIN / 8;
        const uint4* src = (const uint4*)in_;
        for (int c = tid; c < 128 * CPR; c += 256) {
            int r = c / CPR, q = c % CPR;
            uint4 v = (rowbase + r < n) ? src[(size_t)(rowbase + r) * CPR + q]
                                        : make_uint4(0, 0, 0, 0);
            __half* p = &As[r * STR + q * 8];
            ((uint2*)p)[0] = make_uint2(v.x, v.y);
            ((uint2*)p)[1] = make_uint2(v.z, v.w);
        }
    } else {
        constexpr int CPR = DIN / 4;
        const float4* src = (const float4*)in_;
        for (int c = tid; c < 128 * CPR; c += 256) {
            int r = c / CPR, q = c % CPR;
            float4 v = (rowbase + r < n) ? src[(size_t)(rowbase + r) * CPR + q]
                                         : make_float4(0.f, 0.f, 0.f, 0.f);
            uint2 o;
            o.x = h2u(__floats2half2_rn(v.x, v.y));
            o.y = h2u(__floats2half2_rn(v.z, v.w));
            *(uint2*)&As[r * STR + q * 4] = o;
        }
    }
    __syncthreads();

    int g = lane >> 2, t = lane & 3;
    int r0 = wid * 16 + g;
    unsigned a[KC][4];
#pragma unroll
    for (int kc = 0; kc < KC; kc++) {
        int kb = kc * 16 + t * 2;
        a[kc][0] = *(const unsigned*)&As[r0 * STR + kb];
        a[kc][1] = *(const unsigned*)&As[(r0 + 8) * STR + kb];
        a[kc][2] = *(const unsigned*)&As[r0 * STR + kb + 8];
        a[kc][3] = *(const unsigned*)&As[(r0 + 8) * STR + kb + 8];
    }
    int grow0 = rowbase + r0, grow1 = grow0 + 8;
    float di0 = (grow0 < n) ? g_dinv[grow0] : 0.f;
    float di1 = (grow1 < n) ? g_dinv[grow1] : 0.f;
    float accR0 = 0.f, accR1 = 0.f;
#pragma unroll
    for (int nt = 0; nt < NT; nt++) {
        float c0 = 0.f, c1 = 0.f, c2 = 0.f, c3 = 0.f;
#pragma unroll
        for (int kc = 0; kc < KC; kc++) {
            uint2 b = Bs[(nt * KC + kc) * 32 + lane];
            asm volatile(
                "mma.sync.aligned.m16n8k16.row.col.f32.f16.f16.f32 "
                "{%0,%1,%2,%3}, {%4,%5,%6,%7}, {%8,%9}, {%0,%1,%2,%3};\n"
                : "+f"(c0), "+f"(c1), "+f"(c2), "+f"(c3)
                : "r"(a[kc][0]), "r"(a[kc][1]), "r"(a[kc][2]), "r"(a[kc][3]),
                  "r"(b.x), "r"(b.y));
        }
        int col = nt * 8 + t * 2;
        if (EPI >= 1) {
            float s0 = bnS[col], s1 = bnS[col + 1];
            float t0 = bnT[col], t1 = bnT[col + 1];
            c0 = c0 * s0 + t0; c1 = c1 * s1 + t1;
            c2 = c2 * s0 + t0; c3 = c3 * s1 + t1;
            c0 = (c0 > 0.f) ? c0 : expm1f(c0);
            c1 = (c1 > 0.f) ? c1 : expm1f(c1);
            c2 = (c2 > 0.f) ? c2 : expm1f(c2);
            c3 = (c3 > 0.f) ? c3 : expm1f(c3);
        }
        if (EPI == 3) {
            float w0 = __ldg(&W4[col]), w1 = __ldg(&W4[col + 1]);
            accR0 += c0 * w0 + c1 * w1;
            accR1 += c2 * w0 + c3 * w1;
        } else {
            c0 *= di0; c1 *= di0; c2 *= di1; c3 *= di1;
            __half* out = (__half*)out_;
            if (grow0 < n)
                *(unsigned*)&out[(size_t)grow0 * DOUT + col] = h2u(__floats2half2_rn(c0, c1));
            if (grow1 < n)
                *(unsigned*)&out[(size_t)grow1 * DOUT + col] = h2u(__floats2half2_rn(c2, c3));
        }
    }
    if (EPI == 3) {
        accR0 += __shfl_xor_sync(0xffffffffu, accR0, 1);
        accR0 += __shfl_xor_sync(0xffffffffu, accR0, 2);
        accR1 += __shfl_xor_sync(0xffffffffu, accR1, 1);
        accR1 += __shfl_xor_sync(0xffffffffu, accR1, 2);
        float* scal = (float*)out_;
        if (t == 0) {
            if (grow0 < n) scal[grow0] = accR0 * di0;
            if (grow1 < n) scal[grow1] = accR1 * di1;
        }
    }
}

// last layer: scalar rows, batch-8; v = di*(self+sum)+b, ELU, sigmoid
__global__ void agg_last_k(const float* __restrict__ in, const float* __restrict__ b,
                           float* __restrict__ out, int n) {
    int node = blockIdx.x * blockDim.x + threadIdx.x;
    if (node >= n) return;
    float di = g_dinv[node];
    float a0 = in[node], a1 = 0.f, a2 = 0.f, a3 = 0.f;
    float a4 = 0.f, a5 = 0.f, a6 = 0.f, a7 = 0.f;
    int e0 = g_start[node], e1 = e0 + g_indeg[node];
    int e = e0;
    for (; e + 8 <= e1; e += 8) {
        int s0 = __ldg(&g_csrc[e]),     s1 = __ldg(&g_csrc[e + 1]);
        int s2 = __ldg(&g_csrc[e + 2]), s3 = __ldg(&g_csrc[e + 3]);
        int s4 = __ldg(&g_csrc[e + 4]), s5 = __ldg(&g_csrc[e + 5]);
        int s6 = __ldg(&g_csrc[e + 6]), s7 = __ldg(&g_csrc[e + 7]);
        a0 += in[s0]; a1 += in[s1]; a2 += in[s2]; a3 += in[s3];
        a4 += in[s4]; a5 += in[s5]; a6 += in[s6]; a7 += in[s7];
    }
    if (e + 4 <= e1) {
        int s0 = __ldg(&g_csrc[e]),     s1 = __ldg(&g_csrc[e + 1]);
        int s2 = __ldg(&g_csrc[e + 2]), s3 = __ldg(&g_csrc[e + 3]);
        a4 += in[s0]; a5 += in[s1]; a6 += in[s2]; a7 += in[s3];
        e += 4;
    }
    for (; e < e1; e++) a0 += in[__ldg(&g_csrc[e])];
    float v = (((a0 + a1) + (a2 + a3)) + ((a4 + a5) + (a6 + a7))) * di + b[0];
    v = (v > 0.f) ? v : expm1f(v);
    out[node] = 1.f / (1.f + expf(-v));
}

// ---------------- launch ----------------
extern "C" void kernel_launch(void* const* d_in, const int* in_sizes, int n_in,
                              void* d_out, int out_size) {
    const float* x  = (const float*)d_in[0];
    const int*   ei = (const int*)d_in[1];
    const float* W1 = (const float*)d_in[2];  const float* b1 = (const float*)d_in[3];
    const float* W2 = (const float*)d_in[4];  const float* b2 = (const float*)d_in[5];
    const float* W3 = (const float*)d_in[6];  const float* b3 = (const float*)d_in[7];
    const float* W4 = (const float*)d_in[8];  const float* b4 = (const float*)d_in[9];
    const float* g1 = (const float*)d_in[10]; const float* be1 = (const float*)d_in[11];
    const float* rm1 = (const float*)d_in[12]; const float* rv1 = (const float*)d_in[13];
    const float* g2 = (const float*)d_in[14]; const float* be2 = (const float*)d_in[15];
    const float* rm2 = (const float*)d_in[16]; const float* rv2 = (const float*)d_in[17];
    const float* g3 = (const float*)d_in[18]; const float* be3 = (const float*)d_in[19];
    const float* rm3 = (const float*)d_in[20]; const float* rv3 = (const float*)d_in[21];

    int n = in_sizes[0] / 64;       // 100000
    int e = in_sizes[1] / 2;        // 1600000

    __half* hA; cudaGetSymbolAddress((void**)&hA, g_hA);
    __half* hB; cudaGetSymbolAddress((void**)&hB, g_hB);
    float* scal; cudaGetSymbolAddress((void**)&scal, g_scal);
    uint2* w1f; cudaGetSymbolAddress((void**)&w1f, g_w1f);
    uint2* w2f; cudaGetSymbolAddress((void**)&w2f, g_w2f);
    uint2* w3f; cudaGetSymbolAddress((void**)&w3f, g_w3f);
    float* bnS2; cudaGetSymbolAddress((void**)&bnS2, g_bnS2);
    float* bnT2; cudaGetSymbolAddress((void**)&bnT2, g_bnT2);
    float* bnS3; cudaGetSymbolAddress((void**)&bnS3, g_bnS3);
    float* bnT3; cudaGetSymbolAddress((void**)&bnT3, g_bnT3);
    float* out = (float*)d_out;

    int nb_n  = (n + 255) / 256;
    int nb_pp = (MAXN + 255) / 256;
    int nb_e4 = (e / 4 + 255) / 256;
    int nb_g  = (n + 127) / 128;

    cudaStream_t s2;
    cudaStreamCreateWithFlags(&s2, cudaStreamNonBlocking);
    cudaEvent_t evA, evG;
    cudaEventCreateWithFlags(&evA, cudaEventDisableTiming);
    cudaEventCreateWithFlags(&evG, cudaEventDisableTiming);

    // main stream: init counters; side stream: prep (frags + BN, no shared state)
    init_k<<<nb_pp, 256>>>(n);
    prep_k<<<13, 256, 0, s2>>>(W1, W2, W3,
                               b1, g1, be1, rm1, rv1,
                               b2, g2, be2, rm2, rv2,
                               b3, g3, be3, rm3, rv3);

    hist_k<<<nb_e4, 256>>>(ei, e);            // indeg + per-edge rank
    assign_k<<<nb_n, 256>>>(n);               // dinv + segment starts
    cudaEventRecord(evA, 0);

    // gemm1 on side stream: in-stream after prep; waits on assign (dinv valid)
    cudaStreamWaitEvent(s2, evA, 0);
    gemm_mma_k<64, 32, 0, false><<<nb_g, 256, 0, s2>>>(x, w1f, 0, 0, 0, hA, n);
    cudaEventRecord(evG, s2);

    scatter_k<<<nb_e4, 256>>>(ei, e);         // atomic-free
    cudaStreamWaitEvent(0, evG, 0);

    // layer 1 agg (+BN/ELU, *dinv): hA -> hB (w32)
    agg_h_k<4, 1><<<(n * 4 + 255) / 256, 256>>>(hA, hB, n);

    // layer 2: agg (w32), then transform 32->64 (+BN/ELU, *dinv)
    agg_h_k<4, 0><<<(n * 4 + 255) / 256, 256>>>(hB, hA, n);
    gemm_mma_k<32, 64, 1, true><<<nb_g, 256>>>(hA, w2f, bnS2, bnT2, 0, hB, n);

    // layer 3+4 fused: agg (w64), then 64->128 (+BN/ELU) . W4 -> scal (*dinv)
    agg_h_k<8, 0><<<(n * 8 + 255) / 256, 256>>>(hB, hA, n);
    gemm_mma_k<64, 128, 3, true><<<nb_g, 256>>>(hA, w3f, bnS3, bnT3, W4, scal, n);

    // final agg + bias + ELU + sigmoid
    agg_last_k<<<nb_n, 256>>>(scal, b4, out, n);
}